// round 5
// baseline (speedup 1.0000x reference)
#include <cuda_runtime.h>
#include <stdint.h>

// GateLayer: x (4096,4096) f32, idx_l/idx_r (16384,) int, alpha (16384,3) f32,
// y (4096,16384) f32.
#define MDIM    4096
#define GMAX    16384
#define ROWS    8

// Static device scratch (no cudaMalloc allowed)
__device__ __align__(16) int    g_il[GMAX];
__device__ __align__(16) int    g_ir[GMAX];
__device__ __align__(16) float2 g_cf[GMAX];
__device__ int g_is64;

// Scheduled (permuted) per-pair side data: GMAX/2 = 8192 slots
__device__ __align__(16) int2   s_il[GMAX / 2];
__device__ __align__(16) int2   s_ir[GMAX / 2];
__device__ __align__(16) float4 s_cf[GMAX / 2];
__device__ __align__(16) int    s_gd[GMAX / 2];

// ---------------------------------------------------------------------------
// int64-vs-int32 detection (single block): OR of odd 32-bit words within the
// first G words is 0 iff idx is int64 (values < 4096 -> high words all zero).
// ---------------------------------------------------------------------------
__global__ void detect_kernel(const unsigned int* il, const unsigned int* ir, int G) {
    __shared__ unsigned int red[32];
    unsigned int acc = 0;
    for (int i = threadIdx.x * 2 + 1; i < G; i += 2048) acc |= il[i] | ir[i];
    #pragma unroll
    for (int s = 16; s; s >>= 1) acc |= __shfl_xor_sync(0xffffffffu, acc, s);
    if ((threadIdx.x & 31) == 0) red[threadIdx.x >> 5] = acc;
    __syncthreads();
    if (threadIdx.x < 32) {
        unsigned int v = red[threadIdx.x];
        #pragma unroll
        for (int s = 16; s; s >>= 1) v |= __shfl_xor_sync(0xffffffffu, v, s);
        if (threadIdx.x == 0) g_is64 = (v == 0u) ? 1 : 0;
    }
}

// ---------------------------------------------------------------------------
// Fold softmax(alpha) into (c_ab, c_s): y = c_ab*ab + c_s*(a+b); idx -> int32.
// ---------------------------------------------------------------------------
__global__ void prep_kernel(const unsigned int* il_raw, const unsigned int* ir_raw,
                            const float* __restrict__ alpha, int G) {
    int g = blockIdx.x * blockDim.x + threadIdx.x;
    if (g >= G) return;
    int is64 = g_is64;
    int il, ir;
    if (is64) { il = (int)il_raw[2 * g]; ir = (int)ir_raw[2 * g]; }
    else      { il = (int)il_raw[g];     ir = (int)ir_raw[g];     }
    g_il[g] = il;
    g_ir[g] = ir;

    float a0 = alpha[3 * g + 0], a1 = alpha[3 * g + 1], a2 = alpha[3 * g + 2];
    float m  = fmaxf(a0, fmaxf(a1, a2));
    float e0 = expf(a0 - m), e1 = expf(a1 - m), e2 = expf(a2 - m);
    float inv = 1.0f / (e0 + e1 + e2);
    float w0 = e0 * inv, w1 = e1 * inv, w2 = e2 * inv;
    g_cf[g] = make_float2(w0 - w1 - 2.0f * w2, w1 + w2);
}

// ---------------------------------------------------------------------------
// Greedy bank-conflict scheduler. One warp per 64-g window (= one gate-warp
// iteration). Assigns each g-pair a (phase, slot) and an operand orientation
// (a<->b swap, legal: gate is symmetric) minimizing per-phase bank-position
// collisions of the gather LDS.128s. Bank position of column c under the
// smem swizzle: k(c) = ((c<<1) ^ (c>>2)) & 7; quad1 (rows 4-7) is k^1 --
// identical multiplicity structure, so only 4 constraint sets per phase:
// (g-chunk j in {0,1}) x (operand a/b).
// ---------------------------------------------------------------------------
__global__ void greedy_kernel(int G) {
    __shared__ unsigned char cnt[8][4][4][8];   // [warp][phase][set][bucket]
    __shared__ int fill[8][4];
    const int warp = threadIdx.x >> 5, lane = threadIdx.x & 31;
    const int win  = blockIdx.x * 8 + warp;
    if (win >= (G >> 6)) return;

    unsigned char* cw = &cnt[warp][0][0][0];
    for (int i = lane; i < 128; i += 32) cw[i] = 0;
    if (lane < 4) fill[warp][lane] = 0;
    __syncwarp();

    const int base = win << 6;
    for (int p = 0; p < 32; p++) {
        int g0 = base + 2 * p, g1 = g0 + 1;
        int il0 = g_il[g0], ir0 = g_ir[g0];
        int il1 = g_il[g1], ir1 = g_ir[g1];
        int kil0 = ((il0 << 1) ^ (il0 >> 2)) & 7;
        int kir0 = ((ir0 << 1) ^ (ir0 >> 2)) & 7;
        int kil1 = ((il1 << 1) ^ (il1 >> 2)) & 7;
        int kir1 = ((ir1 << 1) ^ (ir1 >> 2)) & 7;

        // lanes 0-15 each evaluate one (phase, orientation) option
        int ph = (lane >> 2) & 3;
        int o  = lane & 3;
        int ka0 = (o & 1) ? kir0 : kil0, kb0 = (o & 1) ? kil0 : kir0;
        int ka1 = (o & 2) ? kir1 : kil1, kb1 = (o & 2) ? kil1 : kir1;

        int f = fill[warp][ph];
        int key;
        if (lane < 16 && f < 8) {
            int c = cnt[warp][ph][0][ka0] + cnt[warp][ph][1][kb0]
                  + cnt[warp][ph][2][ka1] + cnt[warp][ph][3][kb1];
            key = (c << 10) | (f << 5) | lane;
        } else {
            key = (1 << 28) | lane;
        }
        #pragma unroll
        for (int s = 16; s; s >>= 1)
            key = min(key, __shfl_xor_sync(0xffffffffu, key, s));

        if (lane == (key & 31)) {     // winner places the pair
            cnt[warp][ph][0][ka0]++;
            cnt[warp][ph][1][kb0]++;
            cnt[warp][ph][2][ka1]++;
            cnt[warp][ph][3][kb1]++;
            int slot = ph * 8 + fill[warp][ph]++;
            int sidx = (win << 5) + slot;
            int a0 = (o & 1) ? ir0 : il0, b0 = (o & 1) ? il0 : ir0;
            int a1 = (o & 2) ? ir1 : il1, b1 = (o & 2) ? il1 : ir1;
            s_il[sidx] = make_int2(a0, a1);
            s_ir[sidx] = make_int2(b0, b1);
            float2 c0 = g_cf[g0], c1 = g_cf[g1];
            s_cf[sidx] = make_float4(c0.x, c0.y, c1.x, c1.y);
            s_gd[sidx] = g0;
        }
        __syncwarp();
    }
}

// ---------------------------------------------------------------------------
// Main kernel. SMEM holds 8 rows of x TRANSPOSED: column c is two 16-B quads
// (rows 0-3, rows 4-7) at byte B = c*32 + rq*16 + (r&3)*4, swizzled
// P = B ^ ((B>>3)&0x70) so staging is bank-conflict-free. One LDS.128 gathers
// 4 rows of one column. Thread = one scheduled pair (2 g) x 8 rows.
// ---------------------------------------------------------------------------
__device__ __forceinline__ float4 gate4(float4 a, float4 b, float cab, float cs) {
    float4 o;
    o.x = fmaf(cab, a.x * b.x, cs * (a.x + b.x));
    o.y = fmaf(cab, a.y * b.y, cs * (a.y + b.y));
    o.z = fmaf(cab, a.z * b.z, cs * (a.z + b.z));
    o.w = fmaf(cab, a.w * b.w, cs * (a.w + b.w));
    return o;
}

__global__ __launch_bounds__(1024, 1)
void gate_kernel(const float* __restrict__ x, float* __restrict__ y,
                 int G, int gPerBlock) {
    extern __shared__ float sm[];
    char* smb = (char*)sm;
    const int tid  = threadIdx.x;
    const int warp = tid >> 5, lane = tid & 31;
    const int row0   = blockIdx.x * ROWS;
    const int gstart = blockIdx.y * gPerBlock;

    // ---- Stage: 8 rows, transposed + swizzled, conflict-free STS ----
    {
        const int rgrp = lane >> 3;            // 0..3  -> r & 3
        const int csub = lane & 7;             // 0..7
        const int rq   = warp & 1;             // which quad (rows 0-3 vs 4-7)
        const int r    = rq * 4 + rgrp;
        const float4* x4 = (const float4*)(x + (size_t)(row0 + r) * MDIM);
        #pragma unroll
        for (int i = 0; i < 8; i++) {
            int c4 = (warp >> 1) * 8 + csub + i * 128;   // c/4, covers 0..1023
            float4 v = x4[c4];
            int B0 = c4 * 128 + rq * 16 + rgrp * 4;      // byte off for j=0
            int Pb = B0 ^ ((c4 & 7) << 4);               // swizzle (j-invariant)
            *(float*)(smb + (Pb     )) = v.x;            // j offsets XOR 32*j
            *(float*)(smb + (Pb ^ 32)) = v.y;
            *(float*)(smb + (Pb ^ 64)) = v.z;
            *(float*)(smb + (Pb ^ 96)) = v.w;
        }
    }
    __syncthreads();

    float* yrow0 = y + (size_t)row0 * G;

    const int piEnd = (gstart + gPerBlock) >> 1;
    #pragma unroll 2
    for (int pi = (gstart >> 1) + tid; pi < piEnd; pi += 1024) {
        int2   il = __ldg(&s_il[pi]);
        int2   ir = __ldg(&s_ir[pi]);
        float4 cf = __ldg(&s_cf[pi]);   // (cab0, cs0, cab1, cs1)
        int    gd = __ldg(&s_gd[pi]);   // original (pre-permutation) pair base g

        // Swizzled quad addresses: P0 = c*32 ^ ((c*4)&0x70); quad1 = P0 ^ 16
        int PaA = (il.x * 32) ^ ((il.x << 2) & 0x70);
        int PbA = (ir.x * 32) ^ ((ir.x << 2) & 0x70);
        int PaB = (il.y * 32) ^ ((il.y << 2) & 0x70);
        int PbB = (ir.y * 32) ^ ((ir.y << 2) & 0x70);

        float4 aA0 = *(const float4*)(smb + PaA);
        float4 aA1 = *(const float4*)(smb + (PaA ^ 16));
        float4 bA0 = *(const float4*)(smb + PbA);
        float4 bA1 = *(const float4*)(smb + (PbA ^ 16));
        float4 aB0 = *(const float4*)(smb + PaB);
        float4 aB1 = *(const float4*)(smb + (PaB ^ 16));
        float4 bB0 = *(const float4*)(smb + PbB);
        float4 bB1 = *(const float4*)(smb + (PbB ^ 16));

        float4 oA0 = gate4(aA0, bA0, cf.x, cf.y);   // g=gd,   rows 0-3
        float4 oA1 = gate4(aA1, bA1, cf.x, cf.y);   // g=gd,   rows 4-7
        float4 oB0 = gate4(aB0, bB0, cf.z, cf.w);   // g=gd+1, rows 0-3
        float4 oB1 = gate4(aB1, bB1, cf.z, cf.w);   // g=gd+1, rows 4-7

        // 8 coalesced float2 stores; warp covers one contiguous 512-B window
        // per row (permutation is within-window, so the address set is dense).
        float* yp = yrow0 + gd;
        *(float2*)(yp + 0 * (size_t)G) = make_float2(oA0.x, oB0.x);
        *(float2*)(yp + 1 * (size_t)G) = make_float2(oA0.y, oB0.y);
        *(float2*)(yp + 2 * (size_t)G) = make_float2(oA0.z, oB0.z);
        *(float2*)(yp + 3 * (size_t)G) = make_float2(oA0.w, oB0.w);
        *(float2*)(yp + 4 * (size_t)G) = make_float2(oA1.x, oB1.x);
        *(float2*)(yp + 5 * (size_t)G) = make_float2(oA1.y, oB1.y);
        *(float2*)(yp + 6 * (size_t)G) = make_float2(oA1.z, oB1.z);
        *(float2*)(yp + 7 * (size_t)G) = make_float2(oA1.w, oB1.w);
    }
}

// ---------------------------------------------------------------------------
extern "C" void kernel_launch(void* const* d_in, const int* in_sizes, int n_in,
                              void* d_out, int out_size) {
    const float*        x     = (const float*)d_in[0];
    const unsigned int* il    = (const unsigned int*)d_in[1];
    const unsigned int* ir    = (const unsigned int*)d_in[2];
    const float*        alpha = (const float*)d_in[3];
    float*              y     = (float*)d_out;

    const int G = in_sizes[1];               // 16384
    const int B = in_sizes[0] / MDIM;        // 4096

    detect_kernel<<<1, 1024>>>(il, ir, G);
    prep_kernel<<<(G + 255) / 256, 256>>>(il, ir, alpha, G);
    greedy_kernel<<<(G / 64 + 7) / 8, 256>>>(G);

    const int smemBytes = ROWS * MDIM * (int)sizeof(float);  // 131072 B
    cudaFuncSetAttribute(gate_kernel, cudaFuncAttributeMaxDynamicSharedMemorySize,
                         smemBytes);

    dim3 grid(B / ROWS, 2);                  // (512, 2), gPerBlock = G/2
    gate_kernel<<<grid, 1024, smemBytes>>>(x, y, G, G / 2);
}

// round 6
// speedup vs baseline: 1.3700x; 1.3700x over previous
#include <cuda_runtime.h>
#include <stdint.h>

// GateLayer: x (4096,4096) f32, idx_l/idx_r (16384,) int, alpha (16384,3) f32,
// y (4096,16384) f32.
#define MDIM    4096
#define GMAX    16384
#define ROWS    8

// Static device scratch (no cudaMalloc allowed)
__device__ __align__(16) int    g_il[GMAX];
__device__ __align__(16) int    g_ir[GMAX];
__device__ __align__(16) float2 g_cf[GMAX];
__device__ int g_is64;

// ---------------------------------------------------------------------------
// int64-vs-int32 detection, sampled: OR of the first 1024 odd 32-bit words of
// each buffer is 0 iff idx is int64 (values < 4096 -> high words all zero).
// If int32, odd words are random idx values; P(1024 of them all zero) ~ 0.
// ---------------------------------------------------------------------------
__global__ void detect_kernel(const unsigned int* il, const unsigned int* ir, int G) {
    __shared__ unsigned int red[8];
    unsigned int acc = 0;
    int lim = min(G, 2048);
    for (int i = threadIdx.x * 2 + 1; i < lim; i += 512) acc |= il[i] | ir[i];
    #pragma unroll
    for (int s = 16; s; s >>= 1) acc |= __shfl_xor_sync(0xffffffffu, acc, s);
    if ((threadIdx.x & 31) == 0) red[threadIdx.x >> 5] = acc;
    __syncthreads();
    if (threadIdx.x < 8) {
        unsigned int v = red[threadIdx.x];
        v |= __shfl_xor_sync(0xffu, v, 4);
        v |= __shfl_xor_sync(0xffu, v, 2);
        v |= __shfl_xor_sync(0xffu, v, 1);
        if (threadIdx.x == 0) g_is64 = (v == 0u) ? 1 : 0;
    }
}

// ---------------------------------------------------------------------------
// Fold softmax(alpha) into (c_ab, c_s): y = c_ab*ab + c_s*(a+b); idx -> int32.
// ---------------------------------------------------------------------------
__global__ void prep_kernel(const unsigned int* il_raw, const unsigned int* ir_raw,
                            const float* __restrict__ alpha, int G) {
    int g = blockIdx.x * blockDim.x + threadIdx.x;
    if (g >= G) return;
    int is64 = g_is64;
    int il, ir;
    if (is64) { il = (int)il_raw[2 * g]; ir = (int)ir_raw[2 * g]; }
    else      { il = (int)il_raw[g];     ir = (int)ir_raw[g];     }
    g_il[g] = il;
    g_ir[g] = ir;

    float a0 = alpha[3 * g + 0], a1 = alpha[3 * g + 1], a2 = alpha[3 * g + 2];
    float m  = fmaxf(a0, fmaxf(a1, a2));
    float e0 = expf(a0 - m), e1 = expf(a1 - m), e2 = expf(a2 - m);
    float inv = 1.0f / (e0 + e1 + e2);
    float w0 = e0 * inv, w1 = e1 * inv, w2 = e2 * inv;
    g_cf[g] = make_float2(w0 - w1 - 2.0f * w2, w1 + w2);
}

// ---------------------------------------------------------------------------
// Main kernel. SMEM holds 8 rows of x TRANSPOSED: column c is two 16-B quads
// (rows 0-3 at P, rows 4-7 at P^16), P = c*32 ^ ((c<<2)&0x70) (swizzled so
// staging STS is conflict-free). One LDS.128 gathers 4 rows of one column.
// Thread = 4 consecutive g x 8 rows = 32 outputs per iteration:
//   16 LDS.128 + 8 STG.128 + 4 LDG.128 = 28 LSU instructions / 32 outputs.
// Processing is split by row-quad and by g-pair to bound live registers.
// ---------------------------------------------------------------------------
__global__ __launch_bounds__(1024, 1)
void gate_kernel(const float* __restrict__ x, float* __restrict__ y,
                 int G, int gPerBlock) {
    extern __shared__ float sm[];
    char* smb = (char*)sm;
    const int tid  = threadIdx.x;
    const int warp = tid >> 5, lane = tid & 31;
    const int row0   = blockIdx.x * ROWS;
    const int gstart = blockIdx.y * gPerBlock;

    // ---- Stage: 8 rows, transposed + swizzled, conflict-free STS ----
    {
        const int rgrp = lane >> 3;            // 0..3  -> r & 3
        const int csub = lane & 7;             // 0..7
        const int rq   = warp & 1;             // row-quad (rows 0-3 vs 4-7)
        const int r    = rq * 4 + rgrp;
        const float4* x4 = (const float4*)(x + (size_t)(row0 + r) * MDIM);
        #pragma unroll
        for (int i = 0; i < 8; i++) {
            int c4 = (warp >> 1) * 8 + csub + i * 128;   // c/4, covers 0..1023
            float4 v = x4[c4];
            int B0 = c4 * 128 + rq * 16 + rgrp * 4;
            int Pb = B0 ^ ((c4 & 7) << 4);               // swizzle (j-invariant)
            *(float*)(smb + (Pb     )) = v.x;
            *(float*)(smb + (Pb ^ 32)) = v.y;
            *(float*)(smb + (Pb ^ 64)) = v.z;
            *(float*)(smb + (Pb ^ 96)) = v.w;
        }
    }
    __syncthreads();

    float* yrow0 = y + (size_t)row0 * G;

    // 4 g per thread; 1024 threads cover 4096 g per sweep.
    #pragma unroll 2
    for (int gb = gstart + tid * 4; gb < gstart + gPerBlock; gb += 4096) {
        int4   il  = *(const int4*)&g_il[gb];
        int4   ir  = *(const int4*)&g_ir[gb];
        float4 cfA = *(const float4*)&g_cf[gb];       // (cab0,cs0,cab1,cs1)
        float4 cfB = *(const float4*)&g_cf[gb + 2];   // (cab2,cs2,cab3,cs3)

        // Swizzled quad-0 addresses; quad 1 = P ^ 16
        int P0 = (il.x * 32) ^ ((il.x << 2) & 0x70);
        int Q0 = (ir.x * 32) ^ ((ir.x << 2) & 0x70);
        int P1 = (il.y * 32) ^ ((il.y << 2) & 0x70);
        int Q1 = (ir.y * 32) ^ ((ir.y << 2) & 0x70);
        int P2 = (il.z * 32) ^ ((il.z << 2) & 0x70);
        int Q2 = (ir.z * 32) ^ ((ir.z << 2) & 0x70);
        int P3 = (il.w * 32) ^ ((il.w << 2) & 0x70);
        int Q3 = (ir.w * 32) ^ ((ir.w << 2) & 0x70);

        float* yp = yrow0 + gb;

        #pragma unroll
        for (int q = 0; q < 2; q++) {          // row-quad: rows q*4 .. q*4+3
            const int xr = q * 16;
            float4 v0, v1, v2, v3;             // v{r} = outputs (g0,g1,g2,g3) @ row r

            {   // g-pair 0 (g0, g1)
                float4 a0 = *(const float4*)(smb + (P0 ^ xr));
                float4 b0 = *(const float4*)(smb + (Q0 ^ xr));
                float4 a1 = *(const float4*)(smb + (P1 ^ xr));
                float4 b1 = *(const float4*)(smb + (Q1 ^ xr));
                v0.x = fmaf(cfA.x, a0.x * b0.x, cfA.y * (a0.x + b0.x));
                v1.x = fmaf(cfA.x, a0.y * b0.y, cfA.y * (a0.y + b0.y));
                v2.x = fmaf(cfA.x, a0.z * b0.z, cfA.y * (a0.z + b0.z));
                v3.x = fmaf(cfA.x, a0.w * b0.w, cfA.y * (a0.w + b0.w));
                v0.y = fmaf(cfA.z, a1.x * b1.x, cfA.w * (a1.x + b1.x));
                v1.y = fmaf(cfA.z, a1.y * b1.y, cfA.w * (a1.y + b1.y));
                v2.y = fmaf(cfA.z, a1.z * b1.z, cfA.w * (a1.z + b1.z));
                v3.y = fmaf(cfA.z, a1.w * b1.w, cfA.w * (a1.w + b1.w));
            }
            {   // g-pair 1 (g2, g3)
                float4 a2 = *(const float4*)(smb + (P2 ^ xr));
                float4 b2 = *(const float4*)(smb + (Q2 ^ xr));
                float4 a3 = *(const float4*)(smb + (P3 ^ xr));
                float4 b3 = *(const float4*)(smb + (Q3 ^ xr));
                v0.z = fmaf(cfB.x, a2.x * b2.x, cfB.y * (a2.x + b2.x));
                v1.z = fmaf(cfB.x, a2.y * b2.y, cfB.y * (a2.y + b2.y));
                v2.z = fmaf(cfB.x, a2.z * b2.z, cfB.y * (a2.z + b2.z));
                v3.z = fmaf(cfB.x, a2.w * b2.w, cfB.y * (a2.w + b2.w));
                v0.w = fmaf(cfB.z, a3.x * b3.x, cfB.w * (a3.x + b3.x));
                v1.w = fmaf(cfB.z, a3.y * b3.y, cfB.w * (a3.y + b3.y));
                v2.w = fmaf(cfB.z, a3.z * b3.z, cfB.w * (a3.z + b3.z));
                v3.w = fmaf(cfB.z, a3.w * b3.w, cfB.w * (a3.w + b3.w));
            }

            // 4 coalesced STG.128 (warp: 32 lanes x 16 B = one dense 512-B row)
            *(float4*)(yp + (size_t)(q * 4 + 0) * G) = v0;
            *(float4*)(yp + (size_t)(q * 4 + 1) * G) = v1;
            *(float4*)(yp + (size_t)(q * 4 + 2) * G) = v2;
            *(float4*)(yp + (size_t)(q * 4 + 3) * G) = v3;
        }
    }
}

// ---------------------------------------------------------------------------
extern "C" void kernel_launch(void* const* d_in, const int* in_sizes, int n_in,
                              void* d_out, int out_size) {
    const float*        x     = (const float*)d_in[0];
    const unsigned int* il    = (const unsigned int*)d_in[1];
    const unsigned int* ir    = (const unsigned int*)d_in[2];
    const float*        alpha = (const float*)d_in[3];
    float*              y     = (float*)d_out;

    const int G = in_sizes[1];               // 16384
    const int B = in_sizes[0] / MDIM;        // 4096

    detect_kernel<<<1, 256>>>(il, ir, G);
    prep_kernel<<<(G + 255) / 256, 256>>>(il, ir, alpha, G);

    const int smemBytes = ROWS * MDIM * (int)sizeof(float);  // 131072 B
    cudaFuncSetAttribute(gate_kernel, cudaFuncAttributeMaxDynamicSharedMemorySize,
                         smemBytes);

    dim3 grid(B / ROWS, 2);                  // (512, 2), gPerBlock = G/2
    gate_kernel<<<grid, 1024, smemBytes>>>(x, y, G, G / 2);
}

// round 7
// speedup vs baseline: 1.7689x; 1.2912x over previous
#include <cuda_runtime.h>
#include <stdint.h>

// GateLayer: x (4096,4096) f32, idx_l/idx_r (16384,) int, alpha (16384,3) f32,
// y (4096,16384) f32.
#define MDIM    4096
#define GMAX    16384
#define ROWS    4          // rows per tile (one 16-B quad per column)

// Static device scratch (no cudaMalloc allowed)
__device__ __align__(16) int    g_il[GMAX];
__device__ __align__(16) int    g_ir[GMAX];
__device__ __align__(16) float2 g_cf[GMAX];
__device__ int g_is64;

// ---------------------------------------------------------------------------
// int64-vs-int32 detection, sampled: OR of the first 256 odd 32-bit words of
// each buffer is 0 iff idx is int64 (values < 4096 -> high words all zero).
// If int32, odd words are random idx values; P(256 of them all zero) ~ 0.
// ---------------------------------------------------------------------------
__global__ void detect_kernel(const unsigned int* il, const unsigned int* ir, int G) {
    __shared__ unsigned int red[8];
    int lim = min(G, 512);
    int i = threadIdx.x * 2 + 1;
    unsigned int acc = (i < lim) ? (il[i] | ir[i]) : 0u;
    #pragma unroll
    for (int s = 16; s; s >>= 1) acc |= __shfl_xor_sync(0xffffffffu, acc, s);
    if ((threadIdx.x & 31) == 0) red[threadIdx.x >> 5] = acc;
    __syncthreads();
    if (threadIdx.x < 8) {
        unsigned int v = red[threadIdx.x];
        v |= __shfl_xor_sync(0xffu, v, 4);
        v |= __shfl_xor_sync(0xffu, v, 2);
        v |= __shfl_xor_sync(0xffu, v, 1);
        if (threadIdx.x == 0) g_is64 = (v == 0u) ? 1 : 0;
    }
}

// ---------------------------------------------------------------------------
// Fold softmax(alpha) into (c_ab, c_s): y = c_ab*ab + c_s*(a+b); idx -> int32.
// ---------------------------------------------------------------------------
__global__ void prep_kernel(const unsigned int* il_raw, const unsigned int* ir_raw,
                            const float* __restrict__ alpha, int G) {
    int g = blockIdx.x * blockDim.x + threadIdx.x;
    if (g >= G) return;
    int is64 = g_is64;
    int il, ir;
    if (is64) { il = (int)il_raw[2 * g]; ir = (int)ir_raw[2 * g]; }
    else      { il = (int)il_raw[g];     ir = (int)ir_raw[g];     }
    g_il[g] = il;
    g_ir[g] = ir;

    float a0 = alpha[3 * g + 0], a1 = alpha[3 * g + 1], a2 = alpha[3 * g + 2];
    float m  = fmaxf(a0, fmaxf(a1, a2));
    float e0 = expf(a0 - m), e1 = expf(a1 - m), e2 = expf(a2 - m);
    float inv = 1.0f / (e0 + e1 + e2);
    float w0 = e0 * inv, w1 = e1 * inv, w2 = e2 * inv;
    g_cf[g] = make_float2(w0 - w1 - 2.0f * w2, w1 + w2);
}

// ---------------------------------------------------------------------------
// Main kernel, 2 blocks/SM for staging<->gather overlap.
// SMEM holds 4 rows of x TRANSPOSED: column c is ONE 16-B quad (rows 0-3) at
// byte P(c) = (c ^ ((c>>3)&7)) << 4   (bijective; staging STS conflict-free:
// for each float4 component j, the 8 lanes of a phase cover all 8 bank slots).
// One LDS.128 gathers rows 0-3 of one column. Thread = 4 g x 4 rows = 16
// outputs/iter: 8 LDS.128 + 4 STG.128 + 4 LDG.128 = 16 LSU instructions.
// ---------------------------------------------------------------------------
__global__ __launch_bounds__(512, 2)
void gate_kernel(const float* __restrict__ x, float* __restrict__ y,
                 int G, int gPerBlock) {
    extern __shared__ float sm[];
    char* smb = (char*)sm;
    const int tid  = threadIdx.x;
    const int warp = tid >> 5, lane = tid & 31;
    const int row0   = blockIdx.x * ROWS;
    const int gstart = blockIdx.y * gPerBlock;

    // ---- Stage: 4 rows, transposed + swizzled, conflict-free STS ----
    {
        const int r  = lane >> 3;              // 0..3
        const int cs = lane & 7;               // 0..7
        const float4* x4 = (const float4*)(x + (size_t)(row0 + r) * MDIM);
        #pragma unroll
        for (int i = 0; i < 8; i++) {
            int c4 = warp * 8 + cs + i * 128;  // float4 index 0..1023
            float4 v = x4[c4];
            int c0 = c4 * 4;
            #pragma unroll
            for (int j = 0; j < 4; j++) {
                int c = c0 + j;
                int P = ((c ^ ((c >> 3) & 7)) << 4) + r * 4;
                *(float*)(smb + P) = (&v.x)[j];
            }
        }
    }
    __syncthreads();

    float* yrow0 = y + (size_t)row0 * G;

    // 4 g per thread; 512 threads cover 2048 g per sweep.
    #pragma unroll 2
    for (int gb = gstart + tid * 4; gb < gstart + gPerBlock; gb += 2048) {
        int4   il  = *(const int4*)&g_il[gb];
        int4   ir  = *(const int4*)&g_ir[gb];
        float4 cfA = *(const float4*)&g_cf[gb];       // (cab0,cs0,cab1,cs1)
        float4 cfB = *(const float4*)&g_cf[gb + 2];   // (cab2,cs2,cab3,cs3)

        int P0 = (il.x ^ ((il.x >> 3) & 7)) << 4;
        int Q0 = (ir.x ^ ((ir.x >> 3) & 7)) << 4;
        int P1 = (il.y ^ ((il.y >> 3) & 7)) << 4;
        int Q1 = (ir.y ^ ((ir.y >> 3) & 7)) << 4;
        int P2 = (il.z ^ ((il.z >> 3) & 7)) << 4;
        int Q2 = (ir.z ^ ((ir.z >> 3) & 7)) << 4;
        int P3 = (il.w ^ ((il.w >> 3) & 7)) << 4;
        int Q3 = (ir.w ^ ((ir.w >> 3) & 7)) << 4;

        float4 v0, v1, v2, v3;   // v{r} = outputs (g0,g1,g2,g3) at row r

        {   // g-pair 0 (g0, g1)
            float4 a0 = *(const float4*)(smb + P0);
            float4 b0 = *(const float4*)(smb + Q0);
            float4 a1 = *(const float4*)(smb + P1);
            float4 b1 = *(const float4*)(smb + Q1);
            v0.x = fmaf(cfA.x, a0.x * b0.x, cfA.y * (a0.x + b0.x));
            v1.x = fmaf(cfA.x, a0.y * b0.y, cfA.y * (a0.y + b0.y));
            v2.x = fmaf(cfA.x, a0.z * b0.z, cfA.y * (a0.z + b0.z));
            v3.x = fmaf(cfA.x, a0.w * b0.w, cfA.y * (a0.w + b0.w));
            v0.y = fmaf(cfA.z, a1.x * b1.x, cfA.w * (a1.x + b1.x));
            v1.y = fmaf(cfA.z, a1.y * b1.y, cfA.w * (a1.y + b1.y));
            v2.y = fmaf(cfA.z, a1.z * b1.z, cfA.w * (a1.z + b1.z));
            v3.y = fmaf(cfA.z, a1.w * b1.w, cfA.w * (a1.w + b1.w));
        }
        {   // g-pair 1 (g2, g3)
            float4 a2 = *(const float4*)(smb + P2);
            float4 b2 = *(const float4*)(smb + Q2);
            float4 a3 = *(const float4*)(smb + P3);
            float4 b3 = *(const float4*)(smb + Q3);
            v0.z = fmaf(cfB.x, a2.x * b2.x, cfB.y * (a2.x + b2.x));
            v1.z = fmaf(cfB.x, a2.y * b2.y, cfB.y * (a2.y + b2.y));
            v2.z = fmaf(cfB.x, a2.z * b2.z, cfB.y * (a2.z + b2.z));
            v3.z = fmaf(cfB.x, a2.w * b2.w, cfB.y * (a2.w + b2.w));
            v0.w = fmaf(cfB.z, a3.x * b3.x, cfB.w * (a3.x + b3.x));
            v1.w = fmaf(cfB.z, a3.y * b3.y, cfB.w * (a3.y + b3.y));
            v2.w = fmaf(cfB.z, a3.z * b3.z, cfB.w * (a3.z + b3.z));
            v3.w = fmaf(cfB.z, a3.w * b3.w, cfB.w * (a3.w + b3.w));
        }

        // 4 coalesced STG.128 (warp: 32 lanes x 16 B = one dense 512-B row)
        float* yp = yrow0 + gb;
        *(float4*)(yp + 0 * (size_t)G) = v0;
        *(float4*)(yp + 1 * (size_t)G) = v1;
        *(float4*)(yp + 2 * (size_t)G) = v2;
        *(float4*)(yp + 3 * (size_t)G) = v3;
    }
}

// ---------------------------------------------------------------------------
extern "C" void kernel_launch(void* const* d_in, const int* in_sizes, int n_in,
                              void* d_out, int out_size) {
    const float*        x     = (const float*)d_in[0];
    const unsigned int* il    = (const unsigned int*)d_in[1];
    const unsigned int* ir    = (const unsigned int*)d_in[2];
    const float*        alpha = (const float*)d_in[3];
    float*              y     = (float*)d_out;

    const int G = in_sizes[1];               // 16384
    const int B = in_sizes[0] / MDIM;        // 4096

    detect_kernel<<<1, 256>>>(il, ir, G);
    prep_kernel<<<(G + 255) / 256, 256>>>(il, ir, alpha, G);

    const int smemBytes = MDIM * 16;         // 65536 B (one quad per column)
    cudaFuncSetAttribute(gate_kernel, cudaFuncAttributeMaxDynamicSharedMemorySize,
                         smemBytes);

    dim3 grid(B / ROWS, 2);                  // (1024, 2), gPerBlock = G/2
    gate_kernel<<<grid, 512, smemBytes>>>(x, y, G, G / 2);
}